// round 4
// baseline (speedup 1.0000x reference)
#include <cuda_runtime.h>

#define UNITS 10
#define T_IN  50
#define T_OUT 3
#define TPB   128
#define XPAD  129   // 128 elems + 1 pad -> conflict-free smem transpose

__device__ __forceinline__ float fast_sigmoid(float x) {
    // sigmoid(x) = 0.5*tanh(0.5x)+0.5 ; tanh.approx is a single MUFU op
    float t;
    asm("tanh.approx.f32 %0, %1;" : "=f"(t) : "f"(x * 0.5f));
    return fmaf(t, 0.5f, 0.5f);
}

__global__ __launch_bounds__(TPB, 4)   // cap regs at 128 -> >=16 warps/SM
void lstm_seq2seq_kernel(const float* __restrict__ inputs,
                         const float* __restrict__ W1,
                         const float* __restrict__ R1,
                         const float* __restrict__ b1,
                         const float* __restrict__ W2,
                         const float* __restrict__ R2,
                         const float* __restrict__ b2,
                         const float* __restrict__ Wd,
                         const float* __restrict__ bd,
                         float* __restrict__ out) {
    // All weights in NATURAL row-major layout (no transpose): rows of 40 floats.
    __shared__ __align__(16) float sX[T_IN * XPAD];   // [t][elem]
    __shared__ __align__(16) float sR1[UNITS * 40];   // R1[j][g]
    __shared__ __align__(16) float sW2[UNITS * 40];   // W2[j][g]
    __shared__ __align__(16) float sR2[UNITS * 40];   // R2[j][g]
    __shared__ __align__(16) float sW1[40];
    __shared__ __align__(16) float sB1[40];
    __shared__ __align__(16) float sB2[40];
    __shared__ __align__(16) float sWd[12];

    const int tid = threadIdx.x;

    for (int idx = tid; idx < 400; idx += TPB) {
        sR1[idx] = R1[idx];
        sW2[idx] = W2[idx];
        sR2[idx] = R2[idx];
    }
    if (tid < 40) {
        sW1[tid] = W1[tid];
        sB1[tid] = b1[tid];
        sB2[tid] = b2[tid];
    }
    if (tid < 12) sWd[tid] = (tid < 10) ? Wd[tid] : 0.0f;

    // coalesced global -> transposed shared
    const long long blockBase = (long long)blockIdx.x * TPB;
    const float* gx = inputs + blockBase * T_IN;
#pragma unroll 1
    for (int idx = tid; idx < TPB * T_IN; idx += TPB) {
        int elem = idx / T_IN, t = idx % T_IN;
        sX[t * XPAD + elem] = gx[idx];
    }
    __syncthreads();

    // ---------------- LSTM1 ----------------
    float h[UNITS], c[UNITS];
#pragma unroll
    for (int u = 0; u < UNITS; u++) { h[u] = 0.0f; c[u] = 0.0f; }

#pragma unroll 1
    for (int t = 0; t < T_IN; t++) {
        const float x = sX[t * XPAD + tid];
        float z[40];
        // z = b1 + x*W1
#pragma unroll
        for (int q = 0; q < 10; q++) {
            const float4 w = *reinterpret_cast<const float4*>(sW1 + 4 * q);
            const float4 b = *reinterpret_cast<const float4*>(sB1 + 4 * q);
            z[4 * q + 0] = fmaf(x, w.x, b.x);
            z[4 * q + 1] = fmaf(x, w.y, b.y);
            z[4 * q + 2] = fmaf(x, w.z, b.z);
            z[4 * q + 3] = fmaf(x, w.w, b.w);
        }
        // z += h @ R1   (j-outer: weight float4s die immediately)
#pragma unroll
        for (int j = 0; j < UNITS; j++) {
            const float hj = h[j];
            const float* row = sR1 + j * 40;
#pragma unroll
            for (int q = 0; q < 10; q++) {
                const float4 w = *reinterpret_cast<const float4*>(row + 4 * q);
                z[4 * q + 0] = fmaf(hj, w.x, z[4 * q + 0]);
                z[4 * q + 1] = fmaf(hj, w.y, z[4 * q + 1]);
                z[4 * q + 2] = fmaf(hj, w.z, z[4 * q + 2]);
                z[4 * q + 3] = fmaf(hj, w.w, z[4 * q + 3]);
            }
        }
        // gates (Keras order i,f,g,o)
#pragma unroll
        for (int u = 0; u < UNITS; u++) {
            const float gi = fast_sigmoid(z[u]);
            const float gf = fast_sigmoid(z[10 + u]);
            const float gg = fmaxf(z[20 + u], 0.0f);
            const float go = fast_sigmoid(z[30 + u]);
            c[u] = fmaf(gf, c[u], gi * gg);
            h[u] = go * fmaxf(c[u], 0.0f);
        }
    }

    // ---------------- LSTM2 (RepeatVector fused: input = h1 each step) ----
    float h1[UNITS];
#pragma unroll
    for (int u = 0; u < UNITS; u++) { h1[u] = h[u]; h[u] = 0.0f; c[u] = 0.0f; }

    const float bd0 = bd[0];
    const long long e = blockBase + tid;

#pragma unroll 1
    for (int s = 0; s < T_OUT; s++) {
        float z[40];
#pragma unroll
        for (int q = 0; q < 10; q++) {
            const float4 b = *reinterpret_cast<const float4*>(sB2 + 4 * q);
            z[4 * q + 0] = b.x; z[4 * q + 1] = b.y;
            z[4 * q + 2] = b.z; z[4 * q + 3] = b.w;
        }
#pragma unroll
        for (int j = 0; j < UNITS; j++) {
            const float hj = h1[j];
            const float* row = sW2 + j * 40;
#pragma unroll
            for (int q = 0; q < 10; q++) {
                const float4 w = *reinterpret_cast<const float4*>(row + 4 * q);
                z[4 * q + 0] = fmaf(hj, w.x, z[4 * q + 0]);
                z[4 * q + 1] = fmaf(hj, w.y, z[4 * q + 1]);
                z[4 * q + 2] = fmaf(hj, w.z, z[4 * q + 2]);
                z[4 * q + 3] = fmaf(hj, w.w, z[4 * q + 3]);
            }
        }
#pragma unroll
        for (int j = 0; j < UNITS; j++) {
            const float hj = h[j];
            const float* row = sR2 + j * 40;
#pragma unroll
            for (int q = 0; q < 10; q++) {
                const float4 w = *reinterpret_cast<const float4*>(row + 4 * q);
                z[4 * q + 0] = fmaf(hj, w.x, z[4 * q + 0]);
                z[4 * q + 1] = fmaf(hj, w.y, z[4 * q + 1]);
                z[4 * q + 2] = fmaf(hj, w.z, z[4 * q + 2]);
                z[4 * q + 3] = fmaf(hj, w.w, z[4 * q + 3]);
            }
        }
        float acc = bd0;
#pragma unroll
        for (int u = 0; u < UNITS; u++) {
            const float gi = fast_sigmoid(z[u]);
            const float gf = fast_sigmoid(z[10 + u]);
            const float gg = fmaxf(z[20 + u], 0.0f);
            const float go = fast_sigmoid(z[30 + u]);
            c[u] = fmaf(gf, c[u], gi * gg);
            h[u] = go * fmaxf(c[u], 0.0f);
            acc = fmaf(h[u], sWd[u], acc);
        }
        out[e * T_OUT + s] = acc;
    }
}

extern "C" void kernel_launch(void* const* d_in, const int* in_sizes, int n_in,
                              void* d_out, int out_size) {
    const float* inputs = (const float*)d_in[0];
    const float* W1 = (const float*)d_in[1];
    const float* R1 = (const float*)d_in[2];
    const float* b1 = (const float*)d_in[3];
    const float* W2 = (const float*)d_in[4];
    const float* R2 = (const float*)d_in[5];
    const float* b2 = (const float*)d_in[6];
    const float* Wd = (const float*)d_in[7];
    const float* bd = (const float*)d_in[8];
    float* out = (float*)d_out;

    const int B = in_sizes[0] / T_IN;
    const int blocks = (B + TPB - 1) / TPB;
    lstm_seq2seq_kernel<<<blocks, TPB>>>(inputs, W1, R1, b1, W2, R2, b2,
                                         Wd, bd, out);
}

// round 5
// speedup vs baseline: 6.2351x; 6.2351x over previous
#include <cuda_runtime.h>

#define UNITS 10
#define T_IN  50
#define T_OUT 3
#define TPB   128
#define XPAD  129   // 128 elems + 1 pad -> conflict-free smem transpose

__device__ __forceinline__ float fast_sigmoid(float x) {
    // sigmoid(x) = 0.5*tanh(0.5x)+0.5 ; tanh.approx is a single MUFU op
    float t;
    asm("tanh.approx.f32 %0, %1;" : "=f"(t) : "f"(x * 0.5f));
    return fmaf(t, 0.5f, 0.5f);
}

// 10-long dot against gate-major weight row (12-float padded, 16B aligned)
__device__ __forceinline__ float dot10(const float* __restrict__ row,
                                       const float* __restrict__ h, float z) {
    const float4 w0 = *reinterpret_cast<const float4*>(row);
    const float4 w1 = *reinterpret_cast<const float4*>(row + 4);
    const float2 w2 = *reinterpret_cast<const float2*>(row + 8);
    z = fmaf(h[0], w0.x, z); z = fmaf(h[1], w0.y, z);
    z = fmaf(h[2], w0.z, z); z = fmaf(h[3], w0.w, z);
    z = fmaf(h[4], w1.x, z); z = fmaf(h[5], w1.y, z);
    z = fmaf(h[6], w1.z, z); z = fmaf(h[7], w1.w, z);
    z = fmaf(h[8], w2.x, z); z = fmaf(h[9], w2.y, z);
    return z;
}

// 20-long dot (row padded to 20, exact multiple of 4)
__device__ __forceinline__ float dot20(const float* __restrict__ row,
                                       const float* __restrict__ h, float z) {
#pragma unroll
    for (int q = 0; q < 5; q++) {
        const float4 w = *reinterpret_cast<const float4*>(row + 4 * q);
        z = fmaf(h[4 * q + 0], w.x, z);
        z = fmaf(h[4 * q + 1], w.y, z);
        z = fmaf(h[4 * q + 2], w.z, z);
        z = fmaf(h[4 * q + 3], w.w, z);
    }
    return z;
}

__global__ __launch_bounds__(TPB, 4)
void lstm_seq2seq_kernel(const float* __restrict__ inputs,
                         const float* __restrict__ W1,
                         const float* __restrict__ R1,
                         const float* __restrict__ b1,
                         const float* __restrict__ W2,
                         const float* __restrict__ R2,
                         const float* __restrict__ b2,
                         const float* __restrict__ Wd,
                         const float* __restrict__ bd,
                         float* __restrict__ out) {
    __shared__ __align__(16) float sX[T_IN * XPAD];   // [t][elem] transposed inputs
    __shared__ __align__(16) float sR1[40][12];       // gate-major R1, zero-padded
    __shared__ __align__(16) float sM2[40][20];       // [gate][j]: j<10 W2, j>=10 R2
    __shared__ __align__(16) float2 sWB1[40];         // {W1[g], b1[g]}
    __shared__ __align__(16) float sB2[40];
    __shared__ __align__(16) float sWd[12];

    const int tid = threadIdx.x;

    // ---- stage weights (gate-major transpose) ----
    for (int idx = tid; idx < 480; idx += TPB) {      // 40 gates x 12 slots
        int g = idx / 12, j = idx % 12;
        sR1[g][j] = (j < 10) ? R1[j * 40 + g] : 0.0f;
    }
    for (int idx = tid; idx < 800; idx += TPB) {      // 40 gates x 20 slots
        int g = idx / 20, j = idx % 20;
        sM2[g][j] = (j < 10) ? W2[j * 40 + g] : R2[(j - 10) * 40 + g];
    }
    if (tid < 40) {
        sWB1[tid] = make_float2(W1[tid], b1[tid]);
        sB2[tid] = b2[tid];
    }
    if (tid < 12) sWd[tid] = (tid < 10) ? Wd[tid] : 0.0f;

    // ---- stage inputs, coalesced global -> transposed shared ----
    const long long blockBase = (long long)blockIdx.x * TPB;
    const float* gx = inputs + blockBase * T_IN;
#pragma unroll 1
    for (int idx = tid; idx < TPB * T_IN; idx += TPB) {
        int elem = idx / T_IN, t = idx % T_IN;
        sX[t * XPAD + elem] = gx[idx];
    }
    __syncthreads();

    // ---------------- LSTM1 ----------------
    float h[UNITS], c[UNITS];
#pragma unroll
    for (int u = 0; u < UNITS; u++) { h[u] = 0.0f; c[u] = 0.0f; }

#pragma unroll 1
    for (int t = 0; t < T_IN; t++) {
        const float x = sX[t * XPAD + tid];
        float hn[UNITS];
        // unroll 2: 8 concurrent FMA chains, ~80 live regs, no spills
#pragma unroll 2
        for (int u = 0; u < UNITS; u++) {
            const float2 wbI = sWB1[u];
            const float2 wbF = sWB1[10 + u];
            const float2 wbG = sWB1[20 + u];
            const float2 wbO = sWB1[30 + u];
            float zi = dot10(sR1[u],      h, fmaf(x, wbI.x, wbI.y));
            float zf = dot10(sR1[10 + u], h, fmaf(x, wbF.x, wbF.y));
            float zg = dot10(sR1[20 + u], h, fmaf(x, wbG.x, wbG.y));
            float zo = dot10(sR1[30 + u], h, fmaf(x, wbO.x, wbO.y));
            const float gi = fast_sigmoid(zi);
            const float gf = fast_sigmoid(zf);
            const float gg = fmaxf(zg, 0.0f);
            const float go = fast_sigmoid(zo);
            c[u] = fmaf(gf, c[u], gi * gg);
            hn[u] = go * fmaxf(c[u], 0.0f);
        }
#pragma unroll
        for (int u = 0; u < UNITS; u++) h[u] = hn[u];
    }

    // ---------------- LSTM2 (RepeatVector fused) ----------------
    float hh[20];   // [0..9] = h1 (constant input each step), [10..19] = h2
#pragma unroll
    for (int u = 0; u < UNITS; u++) { hh[u] = h[u]; hh[10 + u] = 0.0f; c[u] = 0.0f; }

    const float bd0 = bd[0];
    const long long e = blockBase + tid;

#pragma unroll 1
    for (int s = 0; s < T_OUT; s++) {
        float hn[UNITS];
#pragma unroll 2
        for (int u = 0; u < UNITS; u++) {
            float zi = dot20(sM2[u],      hh, sB2[u]);
            float zf = dot20(sM2[10 + u], hh, sB2[10 + u]);
            float zg = dot20(sM2[20 + u], hh, sB2[20 + u]);
            float zo = dot20(sM2[30 + u], hh, sB2[30 + u]);
            const float gi = fast_sigmoid(zi);
            const float gf = fast_sigmoid(zf);
            const float gg = fmaxf(zg, 0.0f);
            const float go = fast_sigmoid(zo);
            c[u] = fmaf(gf, c[u], gi * gg);
            hn[u] = go * fmaxf(c[u], 0.0f);
        }
        float acc = bd0;
#pragma unroll
        for (int u = 0; u < UNITS; u++) {
            hh[10 + u] = hn[u];
            acc = fmaf(hn[u], sWd[u], acc);
        }
        out[e * T_OUT + s] = acc;
    }
}

extern "C" void kernel_launch(void* const* d_in, const int* in_sizes, int n_in,
                              void* d_out, int out_size) {
    const float* inputs = (const float*)d_in[0];
    const float* W1 = (const float*)d_in[1];
    const float* R1 = (const float*)d_in[2];
    const float* b1 = (const float*)d_in[3];
    const float* W2 = (const float*)d_in[4];
    const float* R2 = (const float*)d_in[5];
    const float* b2 = (const float*)d_in[6];
    const float* Wd = (const float*)d_in[7];
    const float* bd = (const float*)d_in[8];
    float* out = (float*)d_out;

    const int B = in_sizes[0] / T_IN;
    const int blocks = (B + TPB - 1) / TPB;
    lstm_seq2seq_kernel<<<blocks, TPB>>>(inputs, W1, R1, b1, W2, R2, b2,
                                         Wd, bd, out);
}

// round 8
// speedup vs baseline: 6.5620x; 1.0524x over previous
#include <cuda_runtime.h>

#define UNITS  10
#define T_IN   50
#define T_OUT  3
#define TPB    128
#define EPB    256     // elements per block = 2 per thread
#define TCHUNK 25      // time-steps staged per smem chunk
#define XROW   258     // 256 elems + 2 pad

typedef unsigned long long u64;

// ---------- packed f32x2 helpers ----------
__device__ __forceinline__ u64 pack2(float lo, float hi) {
    u64 r;
    asm("mov.b64 %0, {%1, %2};" : "=l"(r)
        : "r"(__float_as_uint(lo)), "r"(__float_as_uint(hi)));
    return r;
}
__device__ __forceinline__ float2 unpack2(u64 v) {
    unsigned lo, hi;
    asm("mov.b64 {%0, %1}, %2;" : "=r"(lo), "=r"(hi) : "l"(v));
    return make_float2(__uint_as_float(lo), __uint_as_float(hi));
}
__device__ __forceinline__ u64 fma2(u64 a, u64 b, u64 c) {
    u64 d;
    asm("fma.rn.f32x2 %0, %1, %2, %3;" : "=l"(d) : "l"(a), "l"(b), "l"(c));
    return d;
}
__device__ __forceinline__ u64 mul2(u64 a, u64 b) {
    u64 d;
    asm("mul.rn.f32x2 %0, %1, %2;" : "=l"(d) : "l"(a), "l"(b));
    return d;
}
__device__ __forceinline__ u64 relu2(u64 a) {
    float2 f = unpack2(a);
    return pack2(fmaxf(f.x, 0.0f), fmaxf(f.y, 0.0f));
}
__device__ __forceinline__ float sigf(float x) {
    // sigmoid(x) = 0.5*tanh(0.5x)+0.5 ; single MUFU
    float t;
    asm("tanh.approx.f32 %0, %1;" : "=f"(t) : "f"(x * 0.5f));
    return fmaf(t, 0.5f, 0.5f);
}
__device__ __forceinline__ u64 sig2(u64 a) {
    float2 f = unpack2(a);
    return pack2(sigf(f.x), sigf(f.y));
}
__device__ __forceinline__ u64 dupf(float w) {
    u64 b = (u64)__float_as_uint(w);
    return (b << 32) | b;
}

// 10-dot: gate-major packed row (12 u64, 16B aligned), 5x LDS.128
__device__ __forceinline__ u64 dot10p(const u64* __restrict__ row, const u64* h, u64 z) {
#pragma unroll
    for (int q = 0; q < 5; q++) {
        const ulonglong2 w = reinterpret_cast<const ulonglong2*>(row)[q];
        z = fma2(h[2 * q],     w.x, z);
        z = fma2(h[2 * q + 1], w.y, z);
    }
    return z;
}
// 20-dot (row = 20 u64)
__device__ __forceinline__ u64 dot20p(const u64* __restrict__ row, const u64* h, u64 z) {
#pragma unroll
    for (int q = 0; q < 10; q++) {
        const ulonglong2 w = reinterpret_cast<const ulonglong2*>(row)[q];
        z = fma2(h[2 * q],     w.x, z);
        z = fma2(h[2 * q + 1], w.y, z);
    }
    return z;
}

__global__ __launch_bounds__(TPB, 4)
void lstm_seq2seq_kernel(const float* __restrict__ inputs,
                         const float* __restrict__ W1,
                         const float* __restrict__ R1,
                         const float* __restrict__ b1,
                         const float* __restrict__ W2,
                         const float* __restrict__ R2,
                         const float* __restrict__ b2,
                         const float* __restrict__ Wd,
                         const float* __restrict__ bd,
                         float* __restrict__ out,
                         long long B) {
    __shared__ __align__(16) float sX[TCHUNK * XROW];   // 25.8 KB input chunk
    __shared__ __align__(16) u64 sR1[40][12];           // gate-major, dup-packed
    __shared__ __align__(16) u64 sM2[40][20];           // [gate][j]: j<10 W2, j>=10 R2
    __shared__ __align__(16) ulonglong2 sWB1[40];       // {dup(W1[g]), dup(b1[g])}
    __shared__ __align__(16) u64 sB2[40];
    __shared__ __align__(16) u64 sWd[10];

    const int tid = threadIdx.x;

    // ---- stage dup-packed weights, gate-major ----
    for (int idx = tid; idx < 480; idx += TPB) {        // 40 x 12
        int g = idx / 12, j = idx % 12;
        sR1[g][j] = (j < 10) ? dupf(R1[j * 40 + g]) : 0ull;
    }
    for (int idx = tid; idx < 800; idx += TPB) {        // 40 x 20
        int g = idx / 20, j = idx % 20;
        sM2[g][j] = (j < 10) ? dupf(W2[j * 40 + g]) : dupf(R2[(j - 10) * 40 + g]);
    }
    if (tid < 40) {
        sWB1[tid] = make_ulonglong2(dupf(W1[tid]), dupf(b1[tid]));
        sB2[tid] = dupf(b2[tid]);
    }
    if (tid < 10) sWd[tid] = dupf(Wd[tid]);

    const long long blockBase = (long long)blockIdx.x * EPB;

    // ---------------- LSTM1 over two 25-step chunks ----------------
    u64 h[UNITS], c[UNITS];
#pragma unroll
    for (int u = 0; u < UNITS; u++) { h[u] = 0ull; c[u] = 0ull; }

#pragma unroll 1
    for (int ch = 0; ch < T_IN / TCHUNK; ch++) {
        __syncthreads();   // weights visible (ch=0) / prev chunk consumed (ch=1)
        // stage 256 elems x 25 steps, transposed, mostly-coalesced
#pragma unroll 1
        for (int idx = tid; idx < EPB * TCHUNK; idx += TPB) {
            int e = idx / TCHUNK, tq = idx % TCHUNK;
            long long eg = blockBase + e;
            if (eg >= B) eg = B - 1;
            sX[tq * XROW + e] = inputs[eg * T_IN + ch * TCHUNK + tq];
        }
        __syncthreads();

#pragma unroll 1
        for (int tq = 0; tq < TCHUNK; tq++) {
            const u64 x2 = pack2(sX[tq * XROW + tid], sX[tq * XROW + 128 + tid]);
            u64 hn[UNITS];
#pragma unroll 2
            for (int u = 0; u < UNITS; u++) {
                const ulonglong2 wbI = sWB1[u];
                const ulonglong2 wbF = sWB1[10 + u];
                const ulonglong2 wbG = sWB1[20 + u];
                const ulonglong2 wbO = sWB1[30 + u];
                u64 zi = dot10p(sR1[u],      h, fma2(x2, wbI.x, wbI.y));
                u64 zf = dot10p(sR1[10 + u], h, fma2(x2, wbF.x, wbF.y));
                u64 zg = dot10p(sR1[20 + u], h, fma2(x2, wbG.x, wbG.y));
                u64 zo = dot10p(sR1[30 + u], h, fma2(x2, wbO.x, wbO.y));
                const u64 gi = sig2(zi);
                const u64 gf = sig2(zf);
                const u64 gg = relu2(zg);
                const u64 go = sig2(zo);
                c[u] = fma2(gf, c[u], mul2(gi, gg));
                hn[u] = mul2(go, relu2(c[u]));
            }
#pragma unroll
            for (int u = 0; u < UNITS; u++) h[u] = hn[u];
        }
    }

    // ---------------- LSTM2 (RepeatVector fused) ----------------
    u64 hh[20];   // [0..9] = h1 (constant per step), [10..19] = h2
#pragma unroll
    for (int u = 0; u < UNITS; u++) { hh[u] = h[u]; hh[10 + u] = 0ull; c[u] = 0ull; }

    const float bd0 = bd[0];
    const u64 bd2 = dupf(bd0);
    const long long e0 = blockBase + tid;
    const long long e1 = e0 + 128;

#pragma unroll 1
    for (int s = 0; s < T_OUT; s++) {
        u64 hn[UNITS];
#pragma unroll 2
        for (int u = 0; u < UNITS; u++) {
            u64 zi = dot20p(sM2[u],      hh, sB2[u]);
            u64 zf = dot20p(sM2[10 + u], hh, sB2[10 + u]);
            u64 zg = dot20p(sM2[20 + u], hh, sB2[20 + u]);
            u64 zo = dot20p(sM2[30 + u], hh, sB2[30 + u]);
            const u64 gi = sig2(zi);
            const u64 gf = sig2(zf);
            const u64 gg = relu2(zg);
            const u64 go = sig2(zo);
            c[u] = fma2(gf, c[u], mul2(gi, gg));
            hn[u] = mul2(go, relu2(c[u]));
        }
        u64 acc = bd2;
#pragma unroll
        for (int u = 0; u < UNITS; u++) {
            hh[10 + u] = hn[u];
            acc = fma2(hn[u], sWd[u], acc);
        }
        const float2 o = unpack2(acc);
        if (e0 < B) out[e0 * T_OUT + s] = o.x;
        if (e1 < B) out[e1 * T_OUT + s] = o.y;
    }
}

extern "C" void kernel_launch(void* const* d_in, const int* in_sizes, int n_in,
                              void* d_out, int out_size) {
    const float* inputs = (const float*)d_in[0];
    const float* W1 = (const float*)d_in[1];
    const float* R1 = (const float*)d_in[2];
    const float* b1 = (const float*)d_in[3];
    const float* W2 = (const float*)d_in[4];
    const float* R2 = (const float*)d_in[5];
    const float* b2 = (const float*)d_in[6];
    const float* Wd = (const float*)d_in[7];
    const float* bd = (const float*)d_in[8];
    float* out = (float*)d_out;

    const long long B = in_sizes[0] / T_IN;
    const int blocks = (int)((B + EPB - 1) / EPB);
    lstm_seq2seq_kernel<<<blocks, TPB>>>(inputs, W1, R1, b1, W2, R2, b2,
                                         Wd, bd, out, B);
}

// round 9
// speedup vs baseline: 7.5851x; 1.1559x over previous
#include <cuda_runtime.h>

#define UNITS  10
#define T_IN   50
#define T_OUT  3
#define TPB    64
#define EPB    256     // elements per block = 4 per thread (2 packed pairs)
#define TCHUNK 10      // time-steps staged per smem chunk
#define XROW   258     // 256 elems + 2 pad

typedef unsigned long long u64;

// ---------- packed f32x2 helpers ----------
__device__ __forceinline__ u64 pack2(float lo, float hi) {
    u64 r;
    asm("mov.b64 %0, {%1, %2};" : "=l"(r)
        : "r"(__float_as_uint(lo)), "r"(__float_as_uint(hi)));
    return r;
}
__device__ __forceinline__ float2 unpack2(u64 v) {
    unsigned lo, hi;
    asm("mov.b64 {%0, %1}, %2;" : "=r"(lo), "=r"(hi) : "l"(v));
    return make_float2(__uint_as_float(lo), __uint_as_float(hi));
}
__device__ __forceinline__ u64 fma2(u64 a, u64 b, u64 c) {
    u64 d;
    asm("fma.rn.f32x2 %0, %1, %2, %3;" : "=l"(d) : "l"(a), "l"(b), "l"(c));
    return d;
}
__device__ __forceinline__ u64 mul2(u64 a, u64 b) {
    u64 d;
    asm("mul.rn.f32x2 %0, %1, %2;" : "=l"(d) : "l"(a), "l"(b));
    return d;
}
__device__ __forceinline__ u64 relu2(u64 a) {
    float2 f = unpack2(a);
    return pack2(fmaxf(f.x, 0.0f), fmaxf(f.y, 0.0f));
}
__device__ __forceinline__ float sigf(float x) {
    float t;
    asm("tanh.approx.f32 %0, %1;" : "=f"(t) : "f"(x * 0.5f));
    return fmaf(t, 0.5f, 0.5f);
}
__device__ __forceinline__ u64 sig2(u64 a) {
    float2 f = unpack2(a);
    return pack2(sigf(f.x), sigf(f.y));
}
__device__ __forceinline__ u64 dupf(float w) {
    u64 b = (u64)__float_as_uint(w);
    return (b << 32) | b;
}

// quad 10-dot: one weight load feeds both packed pairs (a and b)
__device__ __forceinline__ void dot10q(const u64* __restrict__ row,
                                       const u64* ha, const u64* hb,
                                       u64& za, u64& zb) {
#pragma unroll
    for (int q = 0; q < 5; q++) {
        const ulonglong2 w = reinterpret_cast<const ulonglong2*>(row)[q];
        za = fma2(ha[2 * q],     w.x, za);
        zb = fma2(hb[2 * q],     w.x, zb);
        za = fma2(ha[2 * q + 1], w.y, za);
        zb = fma2(hb[2 * q + 1], w.y, zb);
    }
}

__global__ __launch_bounds__(TPB, 5)   // 204-reg cap: headroom, no forced spill
void lstm_seq2seq_kernel(const float* __restrict__ inputs,
                         const float* __restrict__ W1,
                         const float* __restrict__ R1,
                         const float* __restrict__ b1,
                         const float* __restrict__ W2,
                         const float* __restrict__ R2,
                         const float* __restrict__ b2,
                         const float* __restrict__ Wd,
                         const float* __restrict__ bd,
                         float* __restrict__ out,
                         long long B) {
    __shared__ __align__(16) float sX[TCHUNK * XROW];   // ~10.3 KB input chunk
    __shared__ __align__(16) u64 sR1[40][12];           // gate-major, dup-packed
    __shared__ __align__(16) u64 sW2[40][12];           // gate-major W2
    __shared__ __align__(16) u64 sR2[40][12];           // gate-major R2
    __shared__ __align__(16) ulonglong2 sWB1[40];       // {dup(W1[g]), dup(b1[g])}
    __shared__ __align__(16) u64 sB2[40];
    __shared__ __align__(16) u64 sWd[10];

    const int tid = threadIdx.x;

    // ---- stage dup-packed weights, gate-major ----
    for (int idx = tid; idx < 480; idx += TPB) {        // 40 x 12
        int g = idx / 12, j = idx % 12;
        const bool v = (j < 10);
        sR1[g][j] = v ? dupf(R1[j * 40 + g]) : 0ull;
        sW2[g][j] = v ? dupf(W2[j * 40 + g]) : 0ull;
        sR2[g][j] = v ? dupf(R2[j * 40 + g]) : 0ull;
    }
    if (tid < 40) {
        sWB1[tid] = make_ulonglong2(dupf(W1[tid]), dupf(b1[tid]));
        sB2[tid] = dupf(b2[tid]);
    }
    if (tid < 10) sWd[tid] = dupf(Wd[tid]);

    const long long blockBase = (long long)blockIdx.x * EPB;

    // ---------------- LSTM1 over 5 x 10-step chunks ----------------
    u64 ha[UNITS], hb[UNITS], ca[UNITS], cb[UNITS];
#pragma unroll
    for (int u = 0; u < UNITS; u++) { ha[u] = hb[u] = ca[u] = cb[u] = 0ull; }

#pragma unroll 1
    for (int ch = 0; ch < T_IN / TCHUNK; ch++) {
        __syncthreads();   // weights visible (ch=0) / prev chunk consumed
#pragma unroll 1
        for (int idx = tid; idx < EPB * TCHUNK; idx += TPB) {
            int e = idx / TCHUNK, tq = idx % TCHUNK;
            long long eg = blockBase + e;
            if (eg >= B) eg = B - 1;
            sX[tq * XROW + e] = inputs[eg * T_IN + ch * TCHUNK + tq];
        }
        __syncthreads();

#pragma unroll 1
        for (int tq = 0; tq < TCHUNK; tq++) {
            const float* xr = sX + tq * XROW;
            const u64 xa = pack2(xr[tid],       xr[64 + tid]);
            const u64 xb = pack2(xr[128 + tid], xr[192 + tid]);
            u64 hna[UNITS], hnb[UNITS];
#pragma unroll 1
            for (int u = 0; u < UNITS; u++) {
                const ulonglong2 wbI = sWB1[u];
                const ulonglong2 wbF = sWB1[10 + u];
                const ulonglong2 wbG = sWB1[20 + u];
                const ulonglong2 wbO = sWB1[30 + u];
                u64 zia = fma2(xa, wbI.x, wbI.y), zib = fma2(xb, wbI.x, wbI.y);
                u64 zfa = fma2(xa, wbF.x, wbF.y), zfb = fma2(xb, wbF.x, wbF.y);
                u64 zga = fma2(xa, wbG.x, wbG.y), zgb = fma2(xb, wbG.x, wbG.y);
                u64 zoa = fma2(xa, wbO.x, wbO.y), zob = fma2(xb, wbO.x, wbO.y);
                dot10q(sR1[u],      ha, hb, zia, zib);
                dot10q(sR1[10 + u], ha, hb, zfa, zfb);
                dot10q(sR1[20 + u], ha, hb, zga, zgb);
                dot10q(sR1[30 + u], ha, hb, zoa, zob);
                const u64 gia = sig2(zia), gib = sig2(zib);
                const u64 gfa = sig2(zfa), gfb = sig2(zfb);
                const u64 gga = relu2(zga), ggb = relu2(zgb);
                const u64 goa = sig2(zoa), gob = sig2(zob);
                ca[u] = fma2(gfa, ca[u], mul2(gia, gga));
                cb[u] = fma2(gfb, cb[u], mul2(gib, ggb));
                hna[u] = mul2(goa, relu2(ca[u]));
                hnb[u] = mul2(gob, relu2(cb[u]));
            }
#pragma unroll
            for (int u = 0; u < UNITS; u++) { ha[u] = hna[u]; hb[u] = hnb[u]; }
        }
    }

    // ---------------- LSTM2 (RepeatVector fused) ----------------
    u64 h1a[UNITS], h1b[UNITS];
#pragma unroll
    for (int u = 0; u < UNITS; u++) {
        h1a[u] = ha[u]; h1b[u] = hb[u];
        ha[u] = hb[u] = ca[u] = cb[u] = 0ull;
    }

    const u64 bd2 = dupf(bd[0]);
    const long long e0 = blockBase + tid;

#pragma unroll 1
    for (int s = 0; s < T_OUT; s++) {
        u64 hna[UNITS], hnb[UNITS];
#pragma unroll 1
        for (int u = 0; u < UNITS; u++) {
            u64 zia = sB2[u],      zib = zia;
            u64 zfa = sB2[10 + u], zfb = zfa;
            u64 zga = sB2[20 + u], zgb = zga;
            u64 zoa = sB2[30 + u], zob = zoa;
            dot10q(sW2[u],      h1a, h1b, zia, zib);
            dot10q(sW2[10 + u], h1a, h1b, zfa, zfb);
            dot10q(sW2[20 + u], h1a, h1b, zga, zgb);
            dot10q(sW2[30 + u], h1a, h1b, zoa, zob);
            dot10q(sR2[u],      ha, hb, zia, zib);
            dot10q(sR2[10 + u], ha, hb, zfa, zfb);
            dot10q(sR2[20 + u], ha, hb, zga, zgb);
            dot10q(sR2[30 + u], ha, hb, zoa, zob);
            const u64 gia = sig2(zia), gib = sig2(zib);
            const u64 gfa = sig2(zfa), gfb = sig2(zfb);
            const u64 gga = relu2(zga), ggb = relu2(zgb);
            const u64 goa = sig2(zoa), gob = sig2(zob);
            ca[u] = fma2(gfa, ca[u], mul2(gia, gga));
            cb[u] = fma2(gfb, cb[u], mul2(gib, ggb));
            hna[u] = mul2(goa, relu2(ca[u]));
            hnb[u] = mul2(gob, relu2(cb[u]));
        }
        u64 acca = bd2, accb = bd2;
#pragma unroll
        for (int u = 0; u < UNITS; u++) {
            ha[u] = hna[u]; hb[u] = hnb[u];
            acca = fma2(hna[u], sWd[u], acca);
            accb = fma2(hnb[u], sWd[u], accb);
        }
        const float2 oa = unpack2(acca);
        const float2 ob = unpack2(accb);
        if (e0 < B)       out[e0 * T_OUT + s] = oa.x;
        if (e0 + 64 < B)  out[(e0 + 64) * T_OUT + s] = oa.y;
        if (e0 + 128 < B) out[(e0 + 128) * T_OUT + s] = ob.x;
        if (e0 + 192 < B) out[(e0 + 192) * T_OUT + s] = ob.y;
    }
}

extern "C" void kernel_launch(void* const* d_in, const int* in_sizes, int n_in,
                              void* d_out, int out_size) {
    const float* inputs = (const float*)d_in[0];
    const float* W1 = (const float*)d_in[1];
    const float* R1 = (const float*)d_in[2];
    const float* b1 = (const float*)d_in[3];
    const float* W2 = (const float*)d_in[4];
    const float* R2 = (const float*)d_in[5];
    const float* b2 = (const float*)d_in[6];
    const float* Wd = (const float*)d_in[7];
    const float* bd = (const float*)d_in[8];
    float* out = (float*)d_out;

    const long long B = in_sizes[0] / T_IN;
    const int blocks = (int)((B + EPB - 1) / EPB);
    lstm_seq2seq_kernel<<<blocks, TPB>>>(inputs, W1, R1, b1, W2, R2, b2,
                                         Wd, bd, out, B);
}

// round 12
// speedup vs baseline: 8.0546x; 1.0619x over previous
#include <cuda_runtime.h>

#define UNITS  10
#define T_IN   50
#define T_OUT  3
#define TPB    64
#define EPB    256     // elements per block = 4 per thread (2 packed pairs)
#define TCHUNK 10      // time-steps staged per smem chunk
#define XROW   258     // 256 elems + 2 pad

typedef unsigned long long u64;

// ---------- packed f32x2 helpers (identical to Round-9 passing kernel) ----------
__device__ __forceinline__ u64 pack2(float lo, float hi) {
    u64 r;
    asm("mov.b64 %0, {%1, %2};" : "=l"(r)
        : "r"(__float_as_uint(lo)), "r"(__float_as_uint(hi)));
    return r;
}
__device__ __forceinline__ float2 unpack2(u64 v) {
    unsigned lo, hi;
    asm("mov.b64 {%0, %1}, %2;" : "=r"(lo), "=r"(hi) : "l"(v));
    return make_float2(__uint_as_float(lo), __uint_as_float(hi));
}
__device__ __forceinline__ u64 fma2(u64 a, u64 b, u64 c) {
    u64 d;
    asm("fma.rn.f32x2 %0, %1, %2, %3;" : "=l"(d) : "l"(a), "l"(b), "l"(c));
    return d;
}
__device__ __forceinline__ u64 mul2(u64 a, u64 b) {
    u64 d;
    asm("mul.rn.f32x2 %0, %1, %2;" : "=l"(d) : "l"(a), "l"(b));
    return d;
}
__device__ __forceinline__ u64 relu2(u64 a) {
    float2 f = unpack2(a);
    return pack2(fmaxf(f.x, 0.0f), fmaxf(f.y, 0.0f));
}
__device__ __forceinline__ float sigf(float x) {
    float t;
    asm("tanh.approx.f32 %0, %1;" : "=f"(t) : "f"(x * 0.5f));
    return fmaf(t, 0.5f, 0.5f);
}
__device__ __forceinline__ u64 sig2(u64 a) {
    float2 f = unpack2(a);
    return pack2(sigf(f.x), sigf(f.y));
}
// splat a scalar float into both f32x2 lanes: one ALU mov
__device__ __forceinline__ u64 dup2(float w) {
    return pack2(w, w);
}

// quad 10-dot over a SCALAR weight row (12 floats, 16B aligned):
// 3x LDS.128 (vs 5 for dup-packed), 10 splat movs, 20 fma2.
__device__ __forceinline__ void dot10q(const float* __restrict__ row,
                                       const u64* ha, const u64* hb,
                                       u64& za, u64& zb) {
    const float4 wa = reinterpret_cast<const float4*>(row)[0];
    const float4 wb = reinterpret_cast<const float4*>(row)[1];
    const float4 wc = reinterpret_cast<const float4*>(row)[2];  // w8,w9,pad,pad
    u64 w;
    w = dup2(wa.x); za = fma2(ha[0], w, za); zb = fma2(hb[0], w, zb);
    w = dup2(wa.y); za = fma2(ha[1], w, za); zb = fma2(hb[1], w, zb);
    w = dup2(wa.z); za = fma2(ha[2], w, za); zb = fma2(hb[2], w, zb);
    w = dup2(wa.w); za = fma2(ha[3], w, za); zb = fma2(hb[3], w, zb);
    w = dup2(wb.x); za = fma2(ha[4], w, za); zb = fma2(hb[4], w, zb);
    w = dup2(wb.y); za = fma2(ha[5], w, za); zb = fma2(hb[5], w, zb);
    w = dup2(wb.z); za = fma2(ha[6], w, za); zb = fma2(hb[6], w, zb);
    w = dup2(wb.w); za = fma2(ha[7], w, za); zb = fma2(hb[7], w, zb);
    w = dup2(wc.x); za = fma2(ha[8], w, za); zb = fma2(hb[8], w, zb);
    w = dup2(wc.y); za = fma2(ha[9], w, za); zb = fma2(hb[9], w, zb);
}

__global__ __launch_bounds__(TPB, 5)   // 204-reg cap: headroom, no forced spill
void lstm_seq2seq_kernel(const float* __restrict__ inputs,
                         const float* __restrict__ W1,
                         const float* __restrict__ R1,
                         const float* __restrict__ b1,
                         const float* __restrict__ W2,
                         const float* __restrict__ R2,
                         const float* __restrict__ b2,
                         const float* __restrict__ Wd,
                         const float* __restrict__ bd,
                         float* __restrict__ out,
                         long long B) {
    __shared__ __align__(16) float sX[TCHUNK * XROW];   // ~10.3 KB input chunk
    __shared__ __align__(16) float sR1[40][12];         // gate-major SCALAR rows
    __shared__ __align__(16) float sW2[40][12];
    __shared__ __align__(16) float sR2[40][12];
    __shared__ __align__(16) float2 sWB1[40];           // {W1[g], b1[g]}
    __shared__ __align__(16) float sB2[40];
    __shared__ __align__(16) float sWd[10];

    const int tid = threadIdx.x;

    // ---- stage scalar weights, gate-major (transpose) ----
    for (int idx = tid; idx < 480; idx += TPB) {        // 40 x 12
        int g = idx / 12, j = idx % 12;
        const bool v = (j < 10);
        sR1[g][j] = v ? R1[j * 40 + g] : 0.0f;
        sW2[g][j] = v ? W2[j * 40 + g] : 0.0f;
        sR2[g][j] = v ? R2[j * 40 + g] : 0.0f;
    }
    if (tid < 40) {
        sWB1[tid] = make_float2(W1[tid], b1[tid]);
        sB2[tid] = b2[tid];
    }
    if (tid < 10) sWd[tid] = Wd[tid];

    const long long blockBase = (long long)blockIdx.x * EPB;

    // ---------------- LSTM1 over 5 x 10-step chunks ----------------
    u64 ha[UNITS], hb[UNITS], ca[UNITS], cb[UNITS];
#pragma unroll
    for (int u = 0; u < UNITS; u++) { ha[u] = hb[u] = ca[u] = cb[u] = 0ull; }

#pragma unroll 1
    for (int ch = 0; ch < T_IN / TCHUNK; ch++) {
        __syncthreads();   // weights visible (ch=0) / prev chunk consumed
#pragma unroll 1
        for (int idx = tid; idx < EPB * TCHUNK; idx += TPB) {
            int e = idx / TCHUNK, tq = idx % TCHUNK;
            long long eg = blockBase + e;
            if (eg >= B) eg = B - 1;
            sX[tq * XROW + e] = inputs[eg * T_IN + ch * TCHUNK + tq];
        }
        __syncthreads();

#pragma unroll 1
        for (int tq = 0; tq < TCHUNK; tq++) {
            const float* xr = sX + tq * XROW;
            const u64 xa = pack2(xr[tid],       xr[64 + tid]);
            const u64 xb = pack2(xr[128 + tid], xr[192 + tid]);
            u64 hna[UNITS], hnb[UNITS];
#pragma unroll 1
            for (int u = 0; u < UNITS; u++) {
                const float2 fI = sWB1[u];
                const float2 fF = sWB1[10 + u];
                const float2 fG = sWB1[20 + u];
                const float2 fO = sWB1[30 + u];
                const u64 wI = dup2(fI.x), bI = dup2(fI.y);
                const u64 wF = dup2(fF.x), bF = dup2(fF.y);
                const u64 wG = dup2(fG.x), bG = dup2(fG.y);
                const u64 wO = dup2(fO.x), bO = dup2(fO.y);
                u64 zia = fma2(xa, wI, bI), zib = fma2(xb, wI, bI);
                u64 zfa = fma2(xa, wF, bF), zfb = fma2(xb, wF, bF);
                u64 zga = fma2(xa, wG, bG), zgb = fma2(xb, wG, bG);
                u64 zoa = fma2(xa, wO, bO), zob = fma2(xb, wO, bO);
                dot10q(sR1[u],      ha, hb, zia, zib);
                dot10q(sR1[10 + u], ha, hb, zfa, zfb);
                dot10q(sR1[20 + u], ha, hb, zga, zgb);
                dot10q(sR1[30 + u], ha, hb, zoa, zob);
                const u64 gia = sig2(zia), gib = sig2(zib);
                const u64 gfa = sig2(zfa), gfb = sig2(zfb);
                const u64 gga = relu2(zga), ggb = relu2(zgb);
                const u64 goa = sig2(zoa), gob = sig2(zob);
                ca[u] = fma2(gfa, ca[u], mul2(gia, gga));
                cb[u] = fma2(gfb, cb[u], mul2(gib, ggb));
                hna[u] = mul2(goa, relu2(ca[u]));
                hnb[u] = mul2(gob, relu2(cb[u]));
            }
#pragma unroll
            for (int u = 0; u < UNITS; u++) { ha[u] = hna[u]; hb[u] = hnb[u]; }
        }
    }

    // ---------------- LSTM2 (RepeatVector fused) ----------------
    u64 h1a[UNITS], h1b[UNITS];
#pragma unroll
    for (int u = 0; u < UNITS; u++) {
        h1a[u] = ha[u]; h1b[u] = hb[u];
        ha[u] = hb[u] = ca[u] = cb[u] = 0ull;
    }

    const u64 bd2 = dup2(bd[0]);
    const long long e0 = blockBase + tid;

#pragma unroll 1
    for (int s = 0; s < T_OUT; s++) {
        u64 hna[UNITS], hnb[UNITS];
#pragma unroll 1
        for (int u = 0; u < UNITS; u++) {
            u64 zia = dup2(sB2[u]),      zib = zia;
            u64 zfa = dup2(sB2[10 + u]), zfb = zfa;
            u64 zga = dup2(sB2[20 + u]), zgb = zga;
            u64 zoa = dup2(sB2[30 + u]), zob = zoa;
            dot10q(sW2[u],      h1a, h1b, zia, zib);
            dot10q(sW2[10 + u], h1a, h1b, zfa, zfb);
            dot10q(sW2[20 + u], h1a, h1b, zga, zgb);
            dot10q(sW2[30 + u], h1a, h1b, zoa, zob);
            dot10q(sR2[u],      ha, hb, zia, zib);
            dot10q(sR2[10 + u], ha, hb, zfa, zfb);
            dot10q(sR2[20 + u], ha, hb, zga, zgb);
            dot10q(sR2[30 + u], ha, hb, zoa, zob);
            const u64 gia = sig2(zia), gib = sig2(zib);
            const u64 gfa = sig2(zfa), gfb = sig2(zfb);
            const u64 gga = relu2(zga), ggb = relu2(zgb);
            const u64 goa = sig2(zoa), gob = sig2(zob);
            ca[u] = fma2(gfa, ca[u], mul2(gia, gga));
            cb[u] = fma2(gfb, cb[u], mul2(gib, ggb));
            hna[u] = mul2(goa, relu2(ca[u]));
            hnb[u] = mul2(gob, relu2(cb[u]));
        }
        u64 acca = bd2, accb = bd2;
#pragma unroll
        for (int u = 0; u < UNITS; u++) {
            ha[u] = hna[u]; hb[u] = hnb[u];
            const u64 wd = dup2(sWd[u]);
            acca = fma2(hna[u], wd, acca);
            accb = fma2(hnb[u], wd, accb);
        }
        const float2 oa = unpack2(acca);
        const float2 ob = unpack2(accb);
        if (e0 < B)       out[e0 * T_OUT + s] = oa.x;
        if (e0 + 64 < B)  out[(e0 + 64) * T_OUT + s] = oa.y;
        if (e0 + 128 < B) out[(e0 + 128) * T_OUT + s] = ob.x;
        if (e0 + 192 < B) out[(e0 + 192) * T_OUT + s] = ob.y;
    }
}

extern "C" void kernel_launch(void* const* d_in, const int* in_sizes, int n_in,
                              void* d_out, int out_size) {
    const float* inputs = (const float*)d_in[0];
    const float* W1 = (const float*)d_in[1];
    const float* R1 = (const float*)d_in[2];
    const float* b1 = (const float*)d_in[3];
    const float* W2 = (const float*)d_in[4];
    const float* R2 = (const float*)d_in[5];
    const float* b2 = (const float*)d_in[6];
    const float* Wd = (const float*)d_in[7];
    const float* bd = (const float*)d_in[8];
    float* out = (float*)d_out;

    const long long B = in_sizes[0] / T_IN;
    const int blocks = (int)((B + EPB - 1) / EPB);
    lstm_seq2seq_kernel<<<blocks, TPB>>>(inputs, W1, R1, b1, W2, R2, b2,
                                         Wd, bd, out, B);
}

// round 13
// speedup vs baseline: 8.9729x; 1.1140x over previous
#include <cuda_runtime.h>

#define UNITS  10
#define T_IN   50
#define T_OUT  3
#define TPB    128
#define EPB    256     // elements per block = 2 per thread (1 packed pair)
#define TCHUNK 10      // time-steps staged per smem chunk
#define XROW   258     // 256 elems + 2 pad

typedef unsigned long long u64;

// ---------- packed f32x2 helpers ----------
__device__ __forceinline__ u64 pack2(float lo, float hi) {
    u64 r;
    asm("mov.b64 %0, {%1, %2};" : "=l"(r)
        : "r"(__float_as_uint(lo)), "r"(__float_as_uint(hi)));
    return r;
}
__device__ __forceinline__ float2 unpack2(u64 v) {
    unsigned lo, hi;
    asm("mov.b64 {%0, %1}, %2;" : "=r"(lo), "=r"(hi) : "l"(v));
    return make_float2(__uint_as_float(lo), __uint_as_float(hi));
}
__device__ __forceinline__ u64 fma2(u64 a, u64 b, u64 c) {
    u64 d;
    asm("fma.rn.f32x2 %0, %1, %2, %3;" : "=l"(d) : "l"(a), "l"(b), "l"(c));
    return d;
}
__device__ __forceinline__ u64 mul2(u64 a, u64 b) {
    u64 d;
    asm("mul.rn.f32x2 %0, %1, %2;" : "=l"(d) : "l"(a), "l"(b));
    return d;
}
__device__ __forceinline__ u64 relu2(u64 a) {
    float2 f = unpack2(a);
    return pack2(fmaxf(f.x, 0.0f), fmaxf(f.y, 0.0f));
}
__device__ __forceinline__ float tanh_ap(float x) {
    float t;
    asm("tanh.approx.f32 %0, %1;" : "=f"(t) : "f"(x));
    return t;
}
// packed sigmoid: 0.5*tanh(0.5x)+0.5 — packed mul/fma, 2 MUFU
__device__ __forceinline__ u64 sig2(u64 a, u64 half2) {
    const float2 f = unpack2(mul2(a, half2));
    return fma2(pack2(tanh_ap(f.x), tanh_ap(f.y)), half2, half2);
}
// splat a scalar float into both f32x2 lanes
__device__ __forceinline__ u64 dup2(float w) {
    return pack2(w, w);
}

// pair 10-dot over a SCALAR weight row (12 floats, 16B aligned):
// 3x LDS.128, 10 splat movs, 10 fma2.
__device__ __forceinline__ u64 dot10p(const float* __restrict__ row,
                                      const u64* h, u64 z) {
    const float4 wa = reinterpret_cast<const float4*>(row)[0];
    const float4 wb = reinterpret_cast<const float4*>(row)[1];
    const float4 wc = reinterpret_cast<const float4*>(row)[2];  // w8,w9,pad,pad
    z = fma2(h[0], dup2(wa.x), z);
    z = fma2(h[1], dup2(wa.y), z);
    z = fma2(h[2], dup2(wa.z), z);
    z = fma2(h[3], dup2(wa.w), z);
    z = fma2(h[4], dup2(wb.x), z);
    z = fma2(h[5], dup2(wb.y), z);
    z = fma2(h[6], dup2(wb.z), z);
    z = fma2(h[7], dup2(wb.w), z);
    z = fma2(h[8], dup2(wc.x), z);
    z = fma2(h[9], dup2(wc.y), z);
    return z;
}

__global__ __launch_bounds__(TPB, 5)   // 102-reg cap; natural use ~90-100
void lstm_seq2seq_kernel(const float* __restrict__ inputs,
                         const float* __restrict__ W1,
                         const float* __restrict__ R1,
                         const float* __restrict__ b1,
                         const float* __restrict__ W2,
                         const float* __restrict__ R2,
                         const float* __restrict__ b2,
                         const float* __restrict__ Wd,
                         const float* __restrict__ bd,
                         float* __restrict__ out,
                         long long B) {
    __shared__ __align__(16) float sX[TCHUNK * XROW];   // ~10.3 KB input chunk
    __shared__ __align__(16) float sR1[40][12];         // gate-major SCALAR rows
    __shared__ __align__(16) float sW2[40][12];
    __shared__ __align__(16) float sR2[40][12];
    __shared__ __align__(16) float2 sWB1[40];           // {W1[g], b1[g]}
    __shared__ __align__(16) float sB2[40];
    __shared__ __align__(16) float sWd[10];

    const int tid = threadIdx.x;

    // ---- stage scalar weights, gate-major (transpose) ----
    for (int idx = tid; idx < 480; idx += TPB) {        // 40 x 12
        int g = idx / 12, j = idx % 12;
        const bool v = (j < 10);
        sR1[g][j] = v ? R1[j * 40 + g] : 0.0f;
        sW2[g][j] = v ? W2[j * 40 + g] : 0.0f;
        sR2[g][j] = v ? R2[j * 40 + g] : 0.0f;
    }
    if (tid < 40) {
        sWB1[tid] = make_float2(W1[tid], b1[tid]);
        sB2[tid] = b2[tid];
    }
    if (tid < 10) sWd[tid] = Wd[tid];

    const long long blockBase = (long long)blockIdx.x * EPB;
    const u64 half2 = dup2(0.5f);

    // ---------------- LSTM1 over 5 x 10-step chunks ----------------
    u64 h[UNITS], c[UNITS];
#pragma unroll
    for (int u = 0; u < UNITS; u++) { h[u] = 0ull; c[u] = 0ull; }

#pragma unroll 1
    for (int ch = 0; ch < T_IN / TCHUNK; ch++) {
        __syncthreads();   // weights visible (ch=0) / prev chunk consumed
#pragma unroll 1
        for (int idx = tid; idx < EPB * TCHUNK; idx += TPB) {
            int e = idx / TCHUNK, tq = idx % TCHUNK;
            long long eg = blockBase + e;
            if (eg >= B) eg = B - 1;
            sX[tq * XROW + e] = inputs[eg * T_IN + ch * TCHUNK + tq];
        }
        __syncthreads();

#pragma unroll 1
        for (int tq = 0; tq < TCHUNK; tq++) {
            const float* xr = sX + tq * XROW;
            const u64 x2 = pack2(xr[tid], xr[128 + tid]);
            u64 hn[UNITS];
#pragma unroll 1
            for (int u = 0; u < UNITS; u++) {
                const float2 fI = sWB1[u];
                const float2 fF = sWB1[10 + u];
                const float2 fG = sWB1[20 + u];
                const float2 fO = sWB1[30 + u];
                u64 zi = dot10p(sR1[u],      h, fma2(x2, dup2(fI.x), dup2(fI.y)));
                u64 zf = dot10p(sR1[10 + u], h, fma2(x2, dup2(fF.x), dup2(fF.y)));
                u64 zg = dot10p(sR1[20 + u], h, fma2(x2, dup2(fG.x), dup2(fG.y)));
                u64 zo = dot10p(sR1[30 + u], h, fma2(x2, dup2(fO.x), dup2(fO.y)));
                const u64 gi = sig2(zi, half2);
                const u64 gf = sig2(zf, half2);
                const u64 gg = relu2(zg);
                const u64 go = sig2(zo, half2);
                c[u] = fma2(gf, c[u], mul2(gi, gg));
                hn[u] = mul2(go, relu2(c[u]));
            }
#pragma unroll
            for (int u = 0; u < UNITS; u++) h[u] = hn[u];
        }
    }

    // ---------------- LSTM2 (RepeatVector fused) ----------------
    u64 h1[UNITS];
#pragma unroll
    for (int u = 0; u < UNITS; u++) { h1[u] = h[u]; h[u] = 0ull; c[u] = 0ull; }

    const u64 bd2 = dup2(bd[0]);
    const long long e0 = blockBase + tid;

#pragma unroll 1
    for (int s = 0; s < T_OUT; s++) {
        u64 hn[UNITS];
#pragma unroll 1
        for (int u = 0; u < UNITS; u++) {
            u64 zi = dot10p(sR2[u],      h, dot10p(sW2[u],      h1, dup2(sB2[u])));
            u64 zf = dot10p(sR2[10 + u], h, dot10p(sW2[10 + u], h1, dup2(sB2[10 + u])));
            u64 zg = dot10p(sR2[20 + u], h, dot10p(sW2[20 + u], h1, dup2(sB2[20 + u])));
            u64 zo = dot10p(sR2[30 + u], h, dot10p(sW2[30 + u], h1, dup2(sB2[30 + u])));
            const u64 gi = sig2(zi, half2);
            const u64 gf = sig2(zf, half2);
            const u64 gg = relu2(zg);
            const u64 go = sig2(zo, half2);
            c[u] = fma2(gf, c[u], mul2(gi, gg));
            hn[u] = mul2(go, relu2(c[u]));
        }
        u64 acc = bd2;
#pragma unroll
        for (int u = 0; u < UNITS; u++) {
            h[u] = hn[u];
            acc = fma2(hn[u], dup2(sWd[u]), acc);
        }
        const float2 o = unpack2(acc);
        if (e0 < B)       out[e0 * T_OUT + s] = o.x;
        if (e0 + 128 < B) out[(e0 + 128) * T_OUT + s] = o.y;
    }
}

extern "C" void kernel_launch(void* const* d_in, const int* in_sizes, int n_in,
                              void* d_out, int out_size) {
    const float* inputs = (const float*)d_in[0];
    const float* W1 = (const float*)d_in[1];
    const float* R1 = (const float*)d_in[2];
    const float* b1 = (const float*)d_in[3];
    const float* W2 = (const float*)d_in[4];
    const float* R2 = (const float*)d_in[5];
    const float* b2 = (const float*)d_in[6];
    const float* Wd = (const float*)d_in[7];
    const float* bd = (const float*)d_in[8];
    float* out = (float*)d_out;

    const long long B = in_sizes[0] / T_IN;
    const int blocks = (int)((B + EPB - 1) / EPB);
    lstm_seq2seq_kernel<<<blocks, TPB>>>(inputs, W1, R1, b1, W2, R2, b2,
                                         Wd, bd, out, B);
}